// round 2
// baseline (speedup 1.0000x reference)
#include <cuda_runtime.h>
#include <cstdint>

// Problem constants (fixed by reference setup_inputs)
#define BATCH 128
#define SEQ   8192
#define FEAT  32
#define EVAL_POS 4096
#define TRAIN_ELEMS (EVAL_POS * FEAT)    // 131072 per batch
#define BATCH_ELEMS (SEQ * FEAT)         // 262144 per batch
#define TRAIN_VEC4  (TRAIN_ELEMS / 4)    // 32768 float4 per batch
#define BATCH_VEC4  (BATCH_ELEMS / 4)    // 65536 float4 per batch
#define TOTAL_VEC4  ((size_t)BATCH * BATCH_VEC4)  // 8388608

#define FULL_MASK 0xFFFFu                // all 16 classes present

// Scratch: per-batch presence bitmask (values are integers in [0,16))
__device__ unsigned int g_presence[BATCH];

// ---------------------------------------------------------------------------
// Pass 1: presence bitmask over the training prefix of each batch.
// One block per batch; warp-union early exit: once a warp's combined mask
// has all 16 bits set, further reads cannot change the result (mask is
// monotone under OR), so the warp stops. With uniform random classes this
// saturates after ~2 iterations, making pass 1 nearly free while remaining
// correct for arbitrary inputs.
// ---------------------------------------------------------------------------
__global__ __launch_bounds__(1024, 1)
void presence_kernel(const float4* __restrict__ x)
{
    const int b = blockIdx.x;
    const float4* __restrict__ p = x + (size_t)b * BATCH_VEC4;

    unsigned int m = 0;
    // 32768 float4 / 1024 threads = 32 iterations per thread max
    for (int i = threadIdx.x; i < TRAIN_VEC4; i += 1024) {
        float4 v = p[i];
        m |= 1u << (int)v.x;
        m |= 1u << (int)v.y;
        m |= 1u << (int)v.z;
        m |= 1u << (int)v.w;
        // warp-union early exit (safe: OR is monotone; exit only when saturated)
        if (__reduce_or_sync(0xffffffffu, m) == FULL_MASK) { m = FULL_MASK; break; }
    }

    // warp OR-reduce
    m = __reduce_or_sync(0xffffffffu, m);

    __shared__ unsigned int smem[32];
    const int lane = threadIdx.x & 31;
    const int wid  = threadIdx.x >> 5;
    if (lane == 0) smem[wid] = m;
    __syncthreads();

    if (wid == 0) {
        unsigned int mm = smem[lane];   // 32 warps -> all lanes valid
        mm = __reduce_or_sync(0xffffffffu, mm);
        if (lane == 0) g_presence[b] = mm;
    }
}

// ---------------------------------------------------------------------------
// Pass 2: rank every element: rank(v) = popcount(mask & ((1<<v)-1))
// Block = 256 threads x 1 float4; blocks never straddle a batch boundary
// (BATCH_VEC4 = 65536 is a multiple of 256).
// ---------------------------------------------------------------------------
__global__ __launch_bounds__(256)
void rank_kernel(const float4* __restrict__ x, float4* __restrict__ out)
{
    const size_t i = (size_t)blockIdx.x * 256 + threadIdx.x;
    const int b = (int)(i >> 16);            // i / BATCH_VEC4
    const unsigned int m = __ldg(&g_presence[b]);

    float4 v = x[i];
    float4 r;
    r.x = (float)__popc(m & ((1u << (int)v.x) - 1u));
    r.y = (float)__popc(m & ((1u << (int)v.y) - 1u));
    r.z = (float)__popc(m & ((1u << (int)v.z) - 1u));
    r.w = (float)__popc(m & ((1u << (int)v.w) - 1u));
    out[i] = r;
}

// ---------------------------------------------------------------------------
// Launch
// ---------------------------------------------------------------------------
extern "C" void kernel_launch(void* const* d_in, const int* in_sizes, int n_in,
                              void* d_out, int out_size)
{
    const float4* x  = (const float4*)d_in[0];   // [B, S, F] float32
    float4* out      = (float4*)d_out;           // [B, S, F] float32

    presence_kernel<<<BATCH, 1024>>>(x);

    const int blocks = (int)(TOTAL_VEC4 / 256);  // 32768
    rank_kernel<<<blocks, 256>>>(x, out);
}

// round 3
// speedup vs baseline: 1.1260x; 1.1260x over previous
#include <cuda_runtime.h>
#include <cstdint>

// Problem constants (fixed by reference setup_inputs)
#define BATCH 128
#define SEQ   8192
#define FEAT  32
#define EVAL_POS 4096
#define TRAIN_ELEMS (EVAL_POS * FEAT)    // 131072 per batch
#define BATCH_ELEMS (SEQ * FEAT)         // 262144 per batch
#define TRAIN_VEC4  (TRAIN_ELEMS / 4)    // 32768 float4 per batch
#define BATCH_VEC4  (BATCH_ELEMS / 4)    // 65536 float4 per batch

#define FULL_MASK 0xFFFFu                // all 16 classes present

// Fused kernel:
//   - 128 blocks per batch, 256 threads, 2 float4 per thread
//     (128 * 256 * 2 = 65536 = BATCH_VEC4)
//   - warp 0 computes the batch presence mask with early exit (monotone OR:
//     exiting when saturated is always safe). All blocks of a batch read the
//     same leading prefix bytes -> L2 hits; DRAM cost negligible.
//   - then every thread ranks its 2 float4 using popc on the masked prefix.
__global__ __launch_bounds__(256)
void fused_rank_kernel(const float4* __restrict__ x, float4* __restrict__ out)
{
    const int b = blockIdx.x >> 7;                 // 128 blocks per batch
    const size_t base = (size_t)b * BATCH_VEC4;

    __shared__ unsigned int s_mask;

    if (threadIdx.x < 32) {
        const float4* __restrict__ p = x + base;
        unsigned int m = 0;
        for (int i = threadIdx.x; i < TRAIN_VEC4; i += 32) {
            float4 v = __ldg(&p[i]);
            m |= 1u << (int)v.x;
            m |= 1u << (int)v.y;
            m |= 1u << (int)v.z;
            m |= 1u << (int)v.w;
            // warp-union early exit (safe: OR is monotone)
            if (__reduce_or_sync(0xffffffffu, m) == FULL_MASK) { m = FULL_MASK; break; }
        }
        m = __reduce_or_sync(0xffffffffu, m);
        if (threadIdx.x == 0) s_mask = m;
    }
    __syncthreads();
    const unsigned int mask = s_mask;

    // Rank phase: 512 float4 per block, 2 per thread, both loads in flight.
    const size_t i0 = base + ((size_t)(blockIdx.x & 127) << 9) + threadIdx.x;
    const size_t i1 = i0 + 256;

    float4 v0 = __ldcs(&x[i0]);
    float4 v1 = __ldcs(&x[i1]);

    float4 r0, r1;
    r0.x = (float)__popc(mask & ((1u << (int)v0.x) - 1u));
    r0.y = (float)__popc(mask & ((1u << (int)v0.y) - 1u));
    r0.z = (float)__popc(mask & ((1u << (int)v0.z) - 1u));
    r0.w = (float)__popc(mask & ((1u << (int)v0.w) - 1u));
    r1.x = (float)__popc(mask & ((1u << (int)v1.x) - 1u));
    r1.y = (float)__popc(mask & ((1u << (int)v1.y) - 1u));
    r1.z = (float)__popc(mask & ((1u << (int)v1.z) - 1u));
    r1.w = (float)__popc(mask & ((1u << (int)v1.w) - 1u));

    __stcs(&out[i0], r0);
    __stcs(&out[i1], r1);
}

extern "C" void kernel_launch(void* const* d_in, const int* in_sizes, int n_in,
                              void* d_out, int out_size)
{
    const float4* x  = (const float4*)d_in[0];   // [B, S, F] float32
    float4* out      = (float4*)d_out;           // [B, S, F] float32

    const int blocks = BATCH * 128;              // 16384
    fused_rank_kernel<<<blocks, 256>>>(x, out);
}